// round 15
// baseline (speedup 1.0000x reference)
#include <cuda_runtime.h>
#include <cuda_bf16.h>
#include <cstdint>

// LSTM_87067577025240 — Round 14: mma.sync (base-PTX HMMA) tensor pivot.
// tcgen05 is 'a'-gated and the harness targets compute_103 (no 'a') — R13
// proved it. mma.sync.m16n8k16 bf16 is base sm_80+. bf16 3-split / 6-product
// GEMM per step (fp32-level accuracy), weights prepacked in A-fragment order
// (no ldmatrix), streamed 64KB/(kc,split) chunks via cp.async.bulk + mbarrier
// ring. Warp owns 64 h-rows x 4 gates -> epilogue fully register-local.

typedef unsigned int       u32;
typedef unsigned long long u64;

#define SEQ    256
#define HID    512
#define B_TOT  2048
#define C_OUT  10
#define NB     16
#define NCTA   128
#define NTHR   256
#define CHUNKS_PER_STEP 96            // 32 kc x 3 W-splits
#define CHUNK_BYTES     65536
#define N_CHUNKS_TOTAL  (SEQ * CHUNKS_PER_STEP)

// dynamic SMEM offsets (bytes)
#define SM_FULL0  0
#define SM_FULL1  8
#define SM_EMPTY0 16
#define SM_EMPTY1 24
#define SM_XS     64                  // 16 f32
#define SM_RC     128                 // rowconst: [512][2] float4 = 16KB
#define SM_HF     16512               // h fp32 [512][16] = 32KB (last step only)
#define SM_H2F    49280               // h B-frags [3][32][2][32][2] u32 = 48KB
#define SM_WBUF0  98432               // 64KB
#define SM_WBUF1  163968              // 64KB
#define SM_TOTAL  229504

// Prepacked weights: u32[(kc*3+sp)*16384 + ((w*16+mt)*32+t)*4 + i]
// = A-fragment word i of lane t, m-tile mt=(G*4+b), warp w, k-chunk kc, split sp
__device__ __align__(128) u32 g_Wpack[N_CHUNKS_TOTAL / SEQ * 16384];  // 6 MB

// ---------------- PTX helpers ----------------------------------------------
__device__ __forceinline__ u32 smem_u32(const void* p) {
    u32 a;
    asm("{ .reg .u64 t; cvta.to.shared.u64 t, %1; cvt.u32.u64 %0, t; }" : "=r"(a) : "l"(p));
    return a;
}
#define MBAR_INIT(a, c)   asm volatile("mbarrier.init.shared.b64 [%0], %1;" :: "r"(a), "r"(c) : "memory")
#define MBAR_EXPECT(a, b) asm volatile("mbarrier.arrive.expect_tx.shared.b64 _, [%0], %1;" :: "r"(a), "r"(b) : "memory")
#define MBAR_ARRIVE(a)    asm volatile("mbarrier.arrive.shared.b64 _, [%0];" :: "r"(a) : "memory")
#define MBAR_WAIT(a, ph) do { \
    u32 _m = (a), _p = (ph), _d; \
    asm volatile("{\n\t.reg .pred p;\n\t" \
        "mbarrier.try_wait.parity.acquire.cta.shared::cta.b64 p, [%1], %2;\n\t" \
        "selp.b32 %0, 1, 0, p;\n\t}" : "=r"(_d) : "r"(_m), "r"(_p) : "memory"); \
    if (!_d) { \
        asm volatile("{\n\t.reg .pred P1;\n\t" \
            "W_%=:\n\tmbarrier.try_wait.parity.acquire.cta.shared::cta.b64 P1, [%0], %1, 0x989680;\n\t" \
            "@P1 bra.uni D_%=;\n\tbra.uni W_%=;\n\tD_%=:\n\t}" \
            :: "r"(_m), "r"(_p) : "memory"); \
    } } while (0)

__device__ __forceinline__ void bulk_ld(u32 dst, const void* src, u32 bytes, u32 mbar) {
    asm volatile(
        "cp.async.bulk.shared::cluster.global.mbarrier::complete_tx::bytes [%0], [%1], %2, [%3];"
        :: "r"(dst), "l"(src), "r"(bytes), "r"(mbar) : "memory");
}
__device__ __forceinline__ void mma_bf16(float (&d)[4], uint4 a, u64 b) {
    u32 b0 = (u32)b, b1 = (u32)(b >> 32);
    asm("mma.sync.aligned.m16n8k16.row.col.f32.bf16.bf16.f32 "
        "{%0,%1,%2,%3}, {%4,%5,%6,%7}, {%8,%9}, {%0,%1,%2,%3};"
        : "+f"(d[0]), "+f"(d[1]), "+f"(d[2]), "+f"(d[3])
        : "r"(a.x), "r"(a.y), "r"(a.z), "r"(a.w), "r"(b0), "r"(b1));
}

// exact-fp32 nonlinearities (validated: 1.27e-5 over 256 steps on this model)
__device__ __forceinline__ float sigmoid_f(float x) { return 1.0f / (1.0f + __expf(-x)); }
__device__ __forceinline__ float tanh_f(float x) {
    float ax = fabsf(x), e = __expf(-2.0f * ax);
    return copysignf((1.0f - e) / (1.0f + e), x);
}

// bf16 split helpers
__device__ __forceinline__ __nv_bfloat16 split_sp(float v, int sp) {
    __nv_bfloat16 s1 = __float2bfloat16(v);
    if (sp == 0) return s1;
    float r1 = v - __bfloat162float(s1);
    __nv_bfloat16 s2 = __float2bfloat16(r1);
    if (sp == 1) return s2;
    return __float2bfloat16(r1 - __bfloat162float(s2));
}

// ---------------- prepack: fp32 W -> A-fragment-ordered bf16 splits ---------
__global__ void prepack_kernel(const float* __restrict__ wgh, const float* __restrict__ wih,
                               const float* __restrict__ wfh, const float* __restrict__ woh) {
    int id = blockIdx.x * 256 + threadIdx.x;            // [0, 1572864)
    int i  = id & 3, t = (id >> 2) & 31, mt = (id >> 7) & 15, w = (id >> 11) & 7;
    int c3 = id >> 14;                                   // kc*3 + sp
    int kc = c3 / 3, sp = c3 - kc * 3;
    int G = mt >> 2, b = mt & 3;
    int r = w * 64 + b * 16 + (t >> 2) + (i & 1) * 8;    // row within gate block
    int k = kc * 16 + (t & 3) * 2 + (i >> 1) * 8;
    const float* W = (G == 0) ? wgh : (G == 1) ? wih : (G == 2) ? wfh : woh;
    float w0 = W[r * HID + k], w1 = W[r * HID + k + 1];
    __nv_bfloat16 lo = split_sp(w0, sp), hi = split_sp(w1, sp);
    g_Wpack[id] = (u32)__bfloat16_as_ushort(lo) | ((u32)__bfloat16_as_ushort(hi) << 16);
}

// ---------------- chunk consumer: 16 m-tiles x 2 n-tiles x NHS h-splits -----
template <int NHS>
__device__ __forceinline__ void consume(const uint4* __restrict__ abase,
                                        const u64* __restrict__ bbase,
                                        float (&acc)[16][2][4]) {
    u64 b[NHS][2];
#pragma unroll
    for (int hs = 0; hs < NHS; hs++) {
        b[hs][0] = bbase[hs * 2048];
        b[hs][1] = bbase[hs * 2048 + 32];
    }
#pragma unroll
    for (int mt = 0; mt < 16; mt++) {
        uint4 a = abase[mt * 32];
#pragma unroll
        for (int nt = 0; nt < 2; nt++)
#pragma unroll
            for (int hs = 0; hs < NHS; hs++)
                mma_bf16(acc[mt][nt], a, b[hs][nt]);
    }
}

// h B-fragment scatter: write one bf16 triple for (r, j)
__device__ __forceinline__ void store_h_splits(char* h2f, int r, int j, float hv) {
    __nv_bfloat16 s1 = __float2bfloat16(hv);       float f1 = __bfloat162float(s1);
    __nv_bfloat16 s2 = __float2bfloat16(hv - f1);  float f2 = __bfloat162float(s2);
    __nv_bfloat16 s3 = __float2bfloat16(hv - f1 - f2);
    int kc = r >> 4, rem = r & 15;
    int breg = rem >> 3, q2 = (rem & 7) >> 1, half = rem & 1;
    int tt = (j & 7) * 4 + q2;
    int u32idx = kc * 128 + (j >> 3) * 64 + tt * 2 + breg;
    char* p = h2f + u32idx * 4 + half * 2;
    *(__nv_bfloat16*)(p)         = s1;
    *(__nv_bfloat16*)(p + 16384) = s2;             // split stride = 4096 u32
    *(__nv_bfloat16*)(p + 32768) = s3;
}

// ---------------- main persistent kernel -----------------------------------
__global__ __launch_bounds__(NTHR, 1)
void lstm_mma_kernel(const float* __restrict__ x,
                     const float* __restrict__ wgx, const float* __restrict__ wix,
                     const float* __restrict__ wfx, const float* __restrict__ wox,
                     const float* __restrict__ bg,  const float* __restrict__ bi,
                     const float* __restrict__ bf,  const float* __restrict__ bo,
                     const float* __restrict__ wph, const float* __restrict__ bp,
                     const float* __restrict__ h_init, const float* __restrict__ c_init,
                     float* __restrict__ out) {
    extern __shared__ __align__(128) char sm[];
    const u32 smb  = smem_u32(sm);
    const int tid  = threadIdx.x;
    const int lane = tid & 31;
    const int wid  = tid >> 5;
    const int base = blockIdx.x * NB;

    float*  xs   = (float*)(sm + SM_XS);
    float4* rc4  = (float4*)(sm + SM_RC);
    float*  hf32 = (float*)(sm + SM_HF);
    char*   h2f  = sm + SM_H2F;

    if (tid == 0) {
        MBAR_INIT(smb + SM_FULL0, 1);  MBAR_INIT(smb + SM_FULL1, 1);
        MBAR_INIT(smb + SM_EMPTY0, NTHR); MBAR_INIT(smb + SM_EMPTY1, NTHR);
    }
    // row constants
    for (int r = tid; r < HID; r += NTHR) {
        rc4[r * 2]     = make_float4(wgx[r], wix[r], wfx[r], wox[r]);
        rc4[r * 2 + 1] = make_float4(bg[r],  bi[r],  bf[r],  bo[r]);
    }
    // initial h fragments
    for (int idx = tid; idx < HID * NB; idx += NTHR)
        store_h_splits(h2f, idx >> 4, idx & 15, h_init[idx >> 4]);
    if (tid < NB) xs[tid] = x[(base + tid) * SEQ + 0];

    // register c state: [b4][rh][nt][ch]
    float creg[4][2][2][2];
#pragma unroll
    for (int b4 = 0; b4 < 4; b4++)
#pragma unroll
        for (int rh = 0; rh < 2; rh++) {
            float c0 = c_init[wid * 64 + b4 * 16 + (lane >> 2) + rh * 8];
#pragma unroll
            for (int nt = 0; nt < 2; nt++)
#pragma unroll
                for (int ch = 0; ch < 2; ch++) creg[b4][rh][nt][ch] = c0;
        }
    __syncthreads();

    const u32 mbF[2] = { smb + SM_FULL0, smb + SM_FULL1 };
    const u32 mbE[2] = { smb + SM_EMPTY0, smb + SM_EMPTY1 };
    const u32 wboff[2] = { smb + SM_WBUF0, smb + SM_WBUF1 };
    const uint4* abuf[2] = { (const uint4*)(sm + SM_WBUF0) + wid * 512 + lane,
                             (const uint4*)(sm + SM_WBUF1) + wid * 512 + lane };
    const u64* bbase0 = (const u64*)(sm + SM_H2F) + lane;

    int phF[2] = { 0, 0 }, phE[2] = { 0, 0 };
    int n_g = 0;

    if (tid == 0) {   // prologue: fill both buffers
        MBAR_EXPECT(mbF[0], CHUNK_BYTES);
        bulk_ld(wboff[0], (const char*)g_Wpack, CHUNK_BYTES, mbF[0]);
        MBAR_EXPECT(mbF[1], CHUNK_BYTES);
        bulk_ld(wboff[1], (const char*)g_Wpack + CHUNK_BYTES, CHUNK_BYTES, mbF[1]);
    }

    float acc[16][2][4];

    for (int s = 0; s < SEQ; s++) {
#pragma unroll
        for (int mt = 0; mt < 16; mt++)
#pragma unroll
            for (int nt = 0; nt < 2; nt++)
#pragma unroll
                for (int q = 0; q < 4; q++) acc[mt][nt][q] = 0.0f;

        for (int c = 0; c < CHUNKS_PER_STEP; c++) {
            const int st = n_g & 1;
            const int kc = c / 3, sp = c - kc * 3;
            MBAR_WAIT(mbF[st], phF[st]); phF[st] ^= 1;
            const u64* bb = bbase0 + kc * 64;
            if      (sp == 0) consume<3>(abuf[st], bb, acc);
            else if (sp == 1) consume<2>(abuf[st], bb, acc);
            else              consume<1>(abuf[st], bb, acc);
            MBAR_ARRIVE(mbE[st]);
            if (tid == 0) {
                MBAR_WAIT(mbE[st], phE[st]); phE[st] ^= 1;
                if (n_g + 2 < N_CHUNKS_TOTAL) {
                    MBAR_EXPECT(mbF[st], CHUNK_BYTES);
                    bulk_ld(wboff[st],
                            (const char*)g_Wpack + (size_t)((n_g + 2) % CHUNKS_PER_STEP) * CHUNK_BYTES,
                            CHUNK_BYTES, mbF[st]);
                }
            }
            n_g++;
        }
        __syncthreads();   // all warps done reading h2f(s) fragments

        // register-local epilogue: gates -> (c, h), write h fragments
#pragma unroll
        for (int b4 = 0; b4 < 4; b4++)
#pragma unroll
            for (int rh = 0; rh < 2; rh++) {
                const int r = wid * 64 + b4 * 16 + (lane >> 2) + rh * 8;
                const float4 rcw = rc4[r * 2];
                const float4 rcb = rc4[r * 2 + 1];
#pragma unroll
                for (int nt = 0; nt < 2; nt++)
#pragma unroll
                    for (int ch = 0; ch < 2; ch++) {
                        const int j   = nt * 8 + ((lane & 3) << 1) + ch;
                        const int reg = rh * 2 + ch;
                        const float xv = xs[j];
                        const float gv = tanh_f   (acc[b4][nt][reg]      + rcw.x * xv + rcb.x);
                        const float iv = sigmoid_f(acc[4 + b4][nt][reg]  + rcw.y * xv + rcb.y);
                        const float fv = sigmoid_f(acc[8 + b4][nt][reg]  + rcw.z * xv + rcb.z);
                        const float ov = sigmoid_f(acc[12 + b4][nt][reg] + rcw.w * xv + rcb.w);
                        float cc = creg[b4][rh][nt][ch];
                        cc = gv * iv + cc * fv;
                        creg[b4][rh][nt][ch] = cc;
                        const float hv = tanh_f(cc) * ov;
                        store_h_splits(h2f, r, j, hv);
                        if (s == SEQ - 1) hf32[r * NB + j] = hv;
                    }
            }
        if (s + 1 < SEQ && tid < NB) xs[tid] = x[(base + tid) * SEQ + (s + 1)];
        __syncthreads();   // h2f(s+1) visible before next step's B loads
    }

    // final projection: out[b][c] = wph[c][:] . h[:, j] + bp[c]
    if (tid < NB * C_OUT) {
        const int j = tid / C_OUT;
        const int cls = tid - j * C_OUT;
        float accp = bp[cls];
#pragma unroll 8
        for (int k = 0; k < HID; k++) accp += wph[cls * HID + k] * hf32[k * NB + j];
        out[(base + j) * C_OUT + cls] = accp;
    }
}

extern "C" void kernel_launch(void* const* d_in, const int* in_sizes, int n_in,
                              void* d_out, int out_size) {
    const float* x      = (const float*)d_in[0];
    const float* wgx    = (const float*)d_in[1];
    const float* wix    = (const float*)d_in[2];
    const float* wfx    = (const float*)d_in[3];
    const float* wox    = (const float*)d_in[4];
    const float* wgh    = (const float*)d_in[5];
    const float* wih    = (const float*)d_in[6];
    const float* wfh    = (const float*)d_in[7];
    const float* woh    = (const float*)d_in[8];
    const float* bg     = (const float*)d_in[9];
    const float* bi     = (const float*)d_in[10];
    const float* bf     = (const float*)d_in[11];
    const float* bo     = (const float*)d_in[12];
    const float* wph    = (const float*)d_in[13];
    const float* bp     = (const float*)d_in[14];
    const float* h_init = (const float*)d_in[15];
    const float* c_init = (const float*)d_in[16];
    float* out = (float*)d_out;

    cudaFuncSetAttribute(lstm_mma_kernel, cudaFuncAttributeMaxDynamicSharedMemorySize, SM_TOTAL);

    prepack_kernel<<<(CHUNKS_PER_STEP * 16384) / 256, 256>>>(wgh, wih, wfh, woh);
    lstm_mma_kernel<<<NCTA, NTHR, SM_TOTAL>>>(x, wgx, wix, wfx, wox, bg, bi, bf, bo,
                                              wph, bp, h_init, c_init, out);
}

// round 16
// speedup vs baseline: 1.2474x; 1.2474x over previous
#include <cuda_runtime.h>
#include <cuda_bf16.h>
#include <cstdint>

// LSTM_87067577025240 — Round 15: barrier-free weight streaming.
// R14 validated mma.sync + 3-split numerics but lost ~550 cyc/chunk to the
// cp.async.bulk mbarrier handshake (96 chunks x 256 steps). The prepack layout
// is already per-lane A-fragment order, so stream A straight into registers
// with LDG.128 through an 8-deep prefetch ring (validated R4/R11 pattern):
// no SMEM staging, no mbarriers, no producer thread. Only 2 syncthreads/step
// remain (h exchange). Chunk time -> L2 fair-share floor (~1340 cyc).

typedef unsigned int       u32;
typedef unsigned long long u64;

#define SEQ    256
#define HID    512
#define B_TOT  2048
#define C_OUT  10
#define NB     16
#define NCTA   128
#define NTHR   256
#define CHUNKS_PER_STEP 96            // 32 kc x 3 W-splits
#define FRAGS_PER_STEP  (CHUNKS_PER_STEP * 16)   // 1536 per warp

// dynamic SMEM offsets (bytes)
#define SM_XS     64                  // 16 f32
#define SM_RC     128                 // rowconst: [512][2] float4 = 16KB
#define SM_HF     16512               // h fp32 [512][16] = 32KB (last step only)
#define SM_H2F    49280               // h B-frags [3][32 kc][...] = 48KB
#define SM_TOTAL  98432

// Prepacked weights: u32[(kc*3+sp)*16384 + ((w*16+mt)*32+t)*4 + i]
// = A-fragment word i of lane t, m-tile mt=(G*4+b4), warp w, k-chunk kc, split sp
__device__ __align__(128) u32 g_Wpack[CHUNKS_PER_STEP * 16384];  // 6 MB

// ---------------- PTX helpers ----------------------------------------------
__device__ __forceinline__ void mma_bf16(float (&d)[4], uint4 a, u64 b) {
    u32 b0 = (u32)b, b1 = (u32)(b >> 32);
    asm("mma.sync.aligned.m16n8k16.row.col.f32.bf16.bf16.f32 "
        "{%0,%1,%2,%3}, {%4,%5,%6,%7}, {%8,%9}, {%0,%1,%2,%3};"
        : "+f"(d[0]), "+f"(d[1]), "+f"(d[2]), "+f"(d[3])
        : "r"(a.x), "r"(a.y), "r"(a.z), "r"(a.w), "r"(b0), "r"(b1));
}

// exact-fp32 nonlinearities (validated: ~1.26e-5 over 256 steps on this model)
__device__ __forceinline__ float sigmoid_f(float x) { return 1.0f / (1.0f + __expf(-x)); }
__device__ __forceinline__ float tanh_f(float x) {
    float ax = fabsf(x), e = __expf(-2.0f * ax);
    return copysignf((1.0f - e) / (1.0f + e), x);
}

// bf16 split helper
__device__ __forceinline__ __nv_bfloat16 split_sp(float v, int sp) {
    __nv_bfloat16 s1 = __float2bfloat16(v);
    if (sp == 0) return s1;
    float r1 = v - __bfloat162float(s1);
    __nv_bfloat16 s2 = __float2bfloat16(r1);
    if (sp == 1) return s2;
    return __float2bfloat16(r1 - __bfloat162float(s2));
}

// ---------------- prepack: fp32 W -> A-fragment-ordered bf16 splits ---------
__global__ void prepack_kernel(const float* __restrict__ wgh, const float* __restrict__ wih,
                               const float* __restrict__ wfh, const float* __restrict__ woh) {
    int id = blockIdx.x * 256 + threadIdx.x;            // [0, 1572864)
    int i  = id & 3, t = (id >> 2) & 31, mt = (id >> 7) & 15, w = (id >> 11) & 7;
    int c3 = id >> 14;                                   // kc*3 + sp
    int kc = c3 / 3, sp = c3 - kc * 3;
    int G = mt >> 2, b = mt & 3;
    int r = w * 64 + b * 16 + (t >> 2) + (i & 1) * 8;    // row within gate block
    int k = kc * 16 + (t & 3) * 2 + (i >> 1) * 8;
    const float* W = (G == 0) ? wgh : (G == 1) ? wih : (G == 2) ? wfh : woh;
    float w0 = W[r * HID + k], w1 = W[r * HID + k + 1];
    __nv_bfloat16 lo = split_sp(w0, sp), hi = split_sp(w1, sp);
    g_Wpack[id] = (u32)__bfloat16_as_ushort(lo) | ((u32)__bfloat16_as_ushort(hi) << 16);
}

// h B-fragment scatter: write one bf16 triple for (r, j)
__device__ __forceinline__ void store_h_splits(char* h2f, int r, int j, float hv) {
    __nv_bfloat16 s1 = __float2bfloat16(hv);       float f1 = __bfloat162float(s1);
    __nv_bfloat16 s2 = __float2bfloat16(hv - f1);  float f2 = __bfloat162float(s2);
    __nv_bfloat16 s3 = __float2bfloat16(hv - f1 - f2);
    int kc = r >> 4, rem = r & 15;
    int breg = rem >> 3, q2 = (rem & 7) >> 1, half = rem & 1;
    int tt = (j & 7) * 4 + q2;
    int u32idx = kc * 128 + (j >> 3) * 64 + tt * 2 + breg;
    char* p = h2f + u32idx * 4 + half * 2;
    *(__nv_bfloat16*)(p)         = s1;
    *(__nv_bfloat16*)(p + 16384) = s2;             // split stride = 4096 u32
    *(__nv_bfloat16*)(p + 32768) = s3;
}

// ---------------- chunk: 16 m-tiles x 2 n-tiles x NHS h-splits --------------
// Ring-prefetched A: consume ring[mt&7], reload it with fragment (fb+mt) of
// the cyclic per-warp fragment stream (wraps across steps; weights constant).
template <int NHS>
__device__ __forceinline__ void chunk_mma(uint4 (&ring)[8], const uint4* __restrict__ Wp4,
                                          int wbase, int fb,
                                          const u64* __restrict__ bb,
                                          float (&acc)[16][2][4]) {
    u64 b[NHS][2];
#pragma unroll
    for (int hs = 0; hs < NHS; hs++) {
        b[hs][0] = bb[hs * 2048];
        b[hs][1] = bb[hs * 2048 + 32];
    }
#pragma unroll
    for (int mt = 0; mt < 16; mt++) {
        const uint4 a = ring[mt & 7];
        int f = fb + mt;
        if (f >= FRAGS_PER_STEP) f -= FRAGS_PER_STEP;
        ring[mt & 7] = Wp4[(f >> 4) * 4096 + (f & 15) * 32 + wbase];  // LDG.128
#pragma unroll
        for (int nt = 0; nt < 2; nt++)
#pragma unroll
            for (int hs = 0; hs < NHS; hs++)
                mma_bf16(acc[mt][nt], a, b[hs][nt]);
    }
}

// ---------------- main persistent kernel -----------------------------------
__global__ __launch_bounds__(NTHR, 1)
void lstm_mma_kernel(const float* __restrict__ x,
                     const float* __restrict__ wgx, const float* __restrict__ wix,
                     const float* __restrict__ wfx, const float* __restrict__ wox,
                     const float* __restrict__ bg,  const float* __restrict__ bi,
                     const float* __restrict__ bf,  const float* __restrict__ bo,
                     const float* __restrict__ wph, const float* __restrict__ bp,
                     const float* __restrict__ h_init, const float* __restrict__ c_init,
                     float* __restrict__ out) {
    extern __shared__ __align__(128) char sm[];
    const int tid  = threadIdx.x;
    const int lane = tid & 31;
    const int wid  = tid >> 5;
    const int base = blockIdx.x * NB;

    float*  xs   = (float*)(sm + SM_XS);
    float4* rc4  = (float4*)(sm + SM_RC);
    float*  hf32 = (float*)(sm + SM_HF);
    char*   h2f  = sm + SM_H2F;

    // row constants
    for (int r = tid; r < HID; r += NTHR) {
        rc4[r * 2]     = make_float4(wgx[r], wix[r], wfx[r], wox[r]);
        rc4[r * 2 + 1] = make_float4(bg[r],  bi[r],  bf[r],  bo[r]);
    }
    // initial h fragments
    for (int idx = tid; idx < HID * NB; idx += NTHR)
        store_h_splits(h2f, idx >> 4, idx & 15, h_init[idx >> 4]);
    if (tid < NB) xs[tid] = x[(base + tid) * SEQ + 0];

    // register c state: [b4][rh][nt][ch]
    float creg[4][2][2][2];
#pragma unroll
    for (int b4 = 0; b4 < 4; b4++)
#pragma unroll
        for (int rh = 0; rh < 2; rh++) {
            float c0 = c_init[wid * 64 + b4 * 16 + (lane >> 2) + rh * 8];
#pragma unroll
            for (int nt = 0; nt < 2; nt++)
#pragma unroll
                for (int ch = 0; ch < 2; ch++) creg[b4][rh][nt][ch] = c0;
        }
    __syncthreads();

    const uint4* __restrict__ Wp4 = (const uint4*)g_Wpack;
    const int wbase = wid * 512 + lane;              // uint4 index inside a chunk
    const u64* bbase0 = (const u64*)(sm + SM_H2F) + lane;

    // prime the A-fragment ring: frags 0..7 of chunk 0
    uint4 ring[8];
#pragma unroll
    for (int i = 0; i < 8; i++) ring[i] = Wp4[i * 32 + wbase];

    float acc[16][2][4];

    for (int s = 0; s < SEQ; s++) {
#pragma unroll
        for (int mt = 0; mt < 16; mt++)
#pragma unroll
            for (int nt = 0; nt < 2; nt++)
#pragma unroll
                for (int q = 0; q < 4; q++) acc[mt][nt][q] = 0.0f;

        // barrier-free W stream: 96 chunks, ring keeps 8 LDG.128 in flight
#pragma unroll 1
        for (int kc = 0; kc < 32; kc++) {
            const u64* bb = bbase0 + kc * 64;
            const int fb0 = kc * 48 + 8;             // (kc*3+0)*16 + 8
            chunk_mma<3>(ring, Wp4, wbase, fb0,      bb, acc);
            chunk_mma<2>(ring, Wp4, wbase, fb0 + 16, bb, acc);
            chunk_mma<1>(ring, Wp4, wbase, fb0 + 32, bb, acc);
        }
        __syncthreads();   // all warps done reading h2f(s) fragments

        // register-local epilogue: gates -> (c, h), write h fragments
#pragma unroll
        for (int b4 = 0; b4 < 4; b4++)
#pragma unroll
            for (int rh = 0; rh < 2; rh++) {
                const int r = wid * 64 + b4 * 16 + (lane >> 2) + rh * 8;
                const float4 rcw = rc4[r * 2];
                const float4 rcb = rc4[r * 2 + 1];
#pragma unroll
                for (int nt = 0; nt < 2; nt++)
#pragma unroll
                    for (int ch = 0; ch < 2; ch++) {
                        const int j   = nt * 8 + ((lane & 3) << 1) + ch;
                        const int reg = rh * 2 + ch;
                        const float xv = xs[j];
                        const float gv = tanh_f   (acc[b4][nt][reg]      + rcw.x * xv + rcb.x);
                        const float iv = sigmoid_f(acc[4 + b4][nt][reg]  + rcw.y * xv + rcb.y);
                        const float fv = sigmoid_f(acc[8 + b4][nt][reg]  + rcw.z * xv + rcb.z);
                        const float ov = sigmoid_f(acc[12 + b4][nt][reg] + rcw.w * xv + rcb.w);
                        float cc = creg[b4][rh][nt][ch];
                        cc = gv * iv + cc * fv;
                        creg[b4][rh][nt][ch] = cc;
                        const float hv = tanh_f(cc) * ov;
                        store_h_splits(h2f, r, j, hv);
                        if (s == SEQ - 1) hf32[r * NB + j] = hv;
                    }
            }
        if (s + 1 < SEQ && tid < NB) xs[tid] = x[(base + tid) * SEQ + (s + 1)];
        __syncthreads();   // h2f(s+1) visible before next step's B loads
    }

    // final projection: out[b][c] = wph[c][:] . h[:, j] + bp[c]
    if (tid < NB * C_OUT) {
        const int j = tid / C_OUT;
        const int cls = tid - j * C_OUT;
        float accp = bp[cls];
#pragma unroll 8
        for (int k = 0; k < HID; k++) accp += wph[cls * HID + k] * hf32[k * NB + j];
        out[(base + j) * C_OUT + cls] = accp;
    }
}

extern "C" void kernel_launch(void* const* d_in, const int* in_sizes, int n_in,
                              void* d_out, int out_size) {
    const float* x      = (const float*)d_in[0];
    const float* wgx    = (const float*)d_in[1];
    const float* wix    = (const float*)d_in[2];
    const float* wfx    = (const float*)d_in[3];
    const float* wox    = (const float*)d_in[4];
    const float* wgh    = (const float*)d_in[5];
    const float* wih    = (const float*)d_in[6];
    const float* wfh    = (const float*)d_in[7];
    const float* woh    = (const float*)d_in[8];
    const float* bg     = (const float*)d_in[9];
    const float* bi     = (const float*)d_in[10];
    const float* bf     = (const float*)d_in[11];
    const float* bo     = (const float*)d_in[12];
    const float* wph    = (const float*)d_in[13];
    const float* bp     = (const float*)d_in[14];
    const float* h_init = (const float*)d_in[15];
    const float* c_init = (const float*)d_in[16];
    float* out = (float*)d_out;

    cudaFuncSetAttribute(lstm_mma_kernel, cudaFuncAttributeMaxDynamicSharedMemorySize, SM_TOTAL);

    prepack_kernel<<<(CHUNKS_PER_STEP * 16384) / 256, 256>>>(wgh, wih, wfh, woh);
    lstm_mma_kernel<<<NCTA, NTHR, SM_TOTAL>>>(x, wgx, wix, wfx, wox, bg, bi, bf, bo,
                                              wph, bp, h_init, c_init, out);
}

// round 17
// speedup vs baseline: 1.2484x; 1.0008x over previous
#include <cuda_runtime.h>
#include <cuda_bf16.h>
#include <cstdint>

// LSTM_87067577025240 — Round 16: break HMMA accumulator dependency chains.
// R15 ncu: tensor=58.4% with issue=21.8% and L2=44.6% -> the tensor pipe is
// latency-stalled, not bandwidth- or issue-starved. Cause: nt{hs{...}} inner
// order creates distance-1 dependent HMMA chains (3 deep for sp=0) and only
// 2 warps/SMSP exist to cover ~24-32cyc result latency. Fix: process TWO
// m-tiles jointly with hs outer -> same-acc reuse distance 4 (x2 warps = 8
// independent HMMAs in flight/SMSP). Everything else identical to R15.

typedef unsigned int       u32;
typedef unsigned long long u64;

#define SEQ    256
#define HID    512
#define B_TOT  2048
#define C_OUT  10
#define NB     16
#define NCTA   128
#define NTHR   256
#define CHUNKS_PER_STEP 96            // 32 kc x 3 W-splits
#define FRAGS_PER_STEP  (CHUNKS_PER_STEP * 16)   // 1536 per warp

// dynamic SMEM offsets (bytes)
#define SM_XS     64                  // 16 f32
#define SM_RC     128                 // rowconst: [512][2] float4 = 16KB
#define SM_HF     16512               // h fp32 [512][16] = 32KB (last step only)
#define SM_H2F    49280               // h B-frags [3][32 kc][...] = 48KB
#define SM_TOTAL  98432

// Prepacked weights: u32[(kc*3+sp)*16384 + ((w*16+mt)*32+t)*4 + i]
// = A-fragment word i of lane t, m-tile mt=(G*4+b4), warp w, k-chunk kc, split sp
__device__ __align__(128) u32 g_Wpack[CHUNKS_PER_STEP * 16384];  // 6 MB

// ---------------- PTX helpers ----------------------------------------------
__device__ __forceinline__ void mma_bf16(float (&d)[4], uint4 a, u64 b) {
    u32 b0 = (u32)b, b1 = (u32)(b >> 32);
    asm("mma.sync.aligned.m16n8k16.row.col.f32.bf16.bf16.f32 "
        "{%0,%1,%2,%3}, {%4,%5,%6,%7}, {%8,%9}, {%0,%1,%2,%3};"
        : "+f"(d[0]), "+f"(d[1]), "+f"(d[2]), "+f"(d[3])
        : "r"(a.x), "r"(a.y), "r"(a.z), "r"(a.w), "r"(b0), "r"(b1));
}

// exact-fp32 nonlinearities (validated: ~1.26e-5 over 256 steps on this model)
__device__ __forceinline__ float sigmoid_f(float x) { return 1.0f / (1.0f + __expf(-x)); }
__device__ __forceinline__ float tanh_f(float x) {
    float ax = fabsf(x), e = __expf(-2.0f * ax);
    return copysignf((1.0f - e) / (1.0f + e), x);
}

// bf16 split helper
__device__ __forceinline__ __nv_bfloat16 split_sp(float v, int sp) {
    __nv_bfloat16 s1 = __float2bfloat16(v);
    if (sp == 0) return s1;
    float r1 = v - __bfloat162float(s1);
    __nv_bfloat16 s2 = __float2bfloat16(r1);
    if (sp == 1) return s2;
    return __float2bfloat16(r1 - __bfloat162float(s2));
}

// ---------------- prepack: fp32 W -> A-fragment-ordered bf16 splits ---------
__global__ void prepack_kernel(const float* __restrict__ wgh, const float* __restrict__ wih,
                               const float* __restrict__ wfh, const float* __restrict__ woh) {
    int id = blockIdx.x * 256 + threadIdx.x;            // [0, 1572864)
    int i  = id & 3, t = (id >> 2) & 31, mt = (id >> 7) & 15, w = (id >> 11) & 7;
    int c3 = id >> 14;                                   // kc*3 + sp
    int kc = c3 / 3, sp = c3 - kc * 3;
    int G = mt >> 2, b = mt & 3;
    int r = w * 64 + b * 16 + (t >> 2) + (i & 1) * 8;    // row within gate block
    int k = kc * 16 + (t & 3) * 2 + (i >> 1) * 8;
    const float* W = (G == 0) ? wgh : (G == 1) ? wih : (G == 2) ? wfh : woh;
    float w0 = W[r * HID + k], w1 = W[r * HID + k + 1];
    __nv_bfloat16 lo = split_sp(w0, sp), hi = split_sp(w1, sp);
    g_Wpack[id] = (u32)__bfloat16_as_ushort(lo) | ((u32)__bfloat16_as_ushort(hi) << 16);
}

// h B-fragment scatter: write one bf16 triple for (r, j)
__device__ __forceinline__ void store_h_splits(char* h2f, int r, int j, float hv) {
    __nv_bfloat16 s1 = __float2bfloat16(hv);       float f1 = __bfloat162float(s1);
    __nv_bfloat16 s2 = __float2bfloat16(hv - f1);  float f2 = __bfloat162float(s2);
    __nv_bfloat16 s3 = __float2bfloat16(hv - f1 - f2);
    int kc = r >> 4, rem = r & 15;
    int breg = rem >> 3, q2 = (rem & 7) >> 1, half = rem & 1;
    int tt = (j & 7) * 4 + q2;
    int u32idx = kc * 128 + (j >> 3) * 64 + tt * 2 + breg;
    char* p = h2f + u32idx * 4 + half * 2;
    *(__nv_bfloat16*)(p)         = s1;
    *(__nv_bfloat16*)(p + 16384) = s2;             // split stride = 4096 u32
    *(__nv_bfloat16*)(p + 32768) = s3;
}

// ---------------- chunk: 16 m-tiles x 2 n-tiles x NHS h-splits --------------
// Two m-tiles processed jointly, hs OUTER / nt inner: same-accumulator reuse
// distance is 4 mmas (was 1) -> 8 independent HMMAs in flight per SMSP with
// 2 warps. Ring consumption order identical to R15 (mt ascending, 8 ahead).
template <int NHS>
__device__ __forceinline__ void chunk_mma(uint4 (&ring)[8], const uint4* __restrict__ Wp4,
                                          int wbase, int fb,
                                          const u64* __restrict__ bb,
                                          float (&acc)[16][2][4]) {
    u64 b[NHS][2];
#pragma unroll
    for (int hs = 0; hs < NHS; hs++) {
        b[hs][0] = bb[hs * 2048];
        b[hs][1] = bb[hs * 2048 + 32];
    }
#pragma unroll
    for (int mp = 0; mp < 8; mp++) {
        const int mt0 = 2 * mp, mt1 = 2 * mp + 1;
        const uint4 a0 = ring[mt0 & 7];
        const uint4 a1 = ring[mt1 & 7];
        int f0 = fb + mt0; if (f0 >= FRAGS_PER_STEP) f0 -= FRAGS_PER_STEP;
        int f1 = fb + mt1; if (f1 >= FRAGS_PER_STEP) f1 -= FRAGS_PER_STEP;
        ring[mt0 & 7] = Wp4[(f0 >> 4) * 4096 + (f0 & 15) * 32 + wbase];  // LDG.128
        ring[mt1 & 7] = Wp4[(f1 >> 4) * 4096 + (f1 & 15) * 32 + wbase];  // LDG.128
#pragma unroll
        for (int hs = 0; hs < NHS; hs++)
#pragma unroll
            for (int nt = 0; nt < 2; nt++) {
                mma_bf16(acc[mt0][nt], a0, b[hs][nt]);
                mma_bf16(acc[mt1][nt], a1, b[hs][nt]);
            }
    }
}

// ---------------- main persistent kernel -----------------------------------
__global__ __launch_bounds__(NTHR, 1)
void lstm_mma_kernel(const float* __restrict__ x,
                     const float* __restrict__ wgx, const float* __restrict__ wix,
                     const float* __restrict__ wfx, const float* __restrict__ wox,
                     const float* __restrict__ bg,  const float* __restrict__ bi,
                     const float* __restrict__ bf,  const float* __restrict__ bo,
                     const float* __restrict__ wph, const float* __restrict__ bp,
                     const float* __restrict__ h_init, const float* __restrict__ c_init,
                     float* __restrict__ out) {
    extern __shared__ __align__(128) char sm[];
    const int tid  = threadIdx.x;
    const int lane = tid & 31;
    const int wid  = tid >> 5;
    const int base = blockIdx.x * NB;

    float*  xs   = (float*)(sm + SM_XS);
    float4* rc4  = (float4*)(sm + SM_RC);
    float*  hf32 = (float*)(sm + SM_HF);
    char*   h2f  = sm + SM_H2F;

    // row constants
    for (int r = tid; r < HID; r += NTHR) {
        rc4[r * 2]     = make_float4(wgx[r], wix[r], wfx[r], wox[r]);
        rc4[r * 2 + 1] = make_float4(bg[r],  bi[r],  bf[r],  bo[r]);
    }
    // initial h fragments
    for (int idx = tid; idx < HID * NB; idx += NTHR)
        store_h_splits(h2f, idx >> 4, idx & 15, h_init[idx >> 4]);
    if (tid < NB) xs[tid] = x[(base + tid) * SEQ + 0];

    // register c state: [b4][rh][nt][ch]
    float creg[4][2][2][2];
#pragma unroll
    for (int b4 = 0; b4 < 4; b4++)
#pragma unroll
        for (int rh = 0; rh < 2; rh++) {
            float c0 = c_init[wid * 64 + b4 * 16 + (lane >> 2) + rh * 8];
#pragma unroll
            for (int nt = 0; nt < 2; nt++)
#pragma unroll
                for (int ch = 0; ch < 2; ch++) creg[b4][rh][nt][ch] = c0;
        }
    __syncthreads();

    const uint4* __restrict__ Wp4 = (const uint4*)g_Wpack;
    const int wbase = wid * 512 + lane;              // uint4 index inside a chunk
    const u64* bbase0 = (const u64*)(sm + SM_H2F) + lane;

    // prime the A-fragment ring: frags 0..7 of chunk 0
    uint4 ring[8];
#pragma unroll
    for (int i = 0; i < 8; i++) ring[i] = Wp4[i * 32 + wbase];

    float acc[16][2][4];

    for (int s = 0; s < SEQ; s++) {
#pragma unroll
        for (int mt = 0; mt < 16; mt++)
#pragma unroll
            for (int nt = 0; nt < 2; nt++)
#pragma unroll
                for (int q = 0; q < 4; q++) acc[mt][nt][q] = 0.0f;

        // barrier-free W stream: 96 chunks, ring keeps 8 LDG.128 in flight
#pragma unroll 1
        for (int kc = 0; kc < 32; kc++) {
            const u64* bb = bbase0 + kc * 64;
            const int fb0 = kc * 48 + 8;             // (kc*3+0)*16 + 8
            chunk_mma<3>(ring, Wp4, wbase, fb0,      bb, acc);
            chunk_mma<2>(ring, Wp4, wbase, fb0 + 16, bb, acc);
            chunk_mma<1>(ring, Wp4, wbase, fb0 + 32, bb, acc);
        }
        __syncthreads();   // all warps done reading h2f(s) fragments

        // register-local epilogue: gates -> (c, h), write h fragments
#pragma unroll
        for (int b4 = 0; b4 < 4; b4++)
#pragma unroll
            for (int rh = 0; rh < 2; rh++) {
                const int r = wid * 64 + b4 * 16 + (lane >> 2) + rh * 8;
                const float4 rcw = rc4[r * 2];
                const float4 rcb = rc4[r * 2 + 1];
#pragma unroll
                for (int nt = 0; nt < 2; nt++)
#pragma unroll
                    for (int ch = 0; ch < 2; ch++) {
                        const int j   = nt * 8 + ((lane & 3) << 1) + ch;
                        const int reg = rh * 2 + ch;
                        const float xv = xs[j];
                        const float gv = tanh_f   (acc[b4][nt][reg]      + rcw.x * xv + rcb.x);
                        const float iv = sigmoid_f(acc[4 + b4][nt][reg]  + rcw.y * xv + rcb.y);
                        const float fv = sigmoid_f(acc[8 + b4][nt][reg]  + rcw.z * xv + rcb.z);
                        const float ov = sigmoid_f(acc[12 + b4][nt][reg] + rcw.w * xv + rcb.w);
                        float cc = creg[b4][rh][nt][ch];
                        cc = gv * iv + cc * fv;
                        creg[b4][rh][nt][ch] = cc;
                        const float hv = tanh_f(cc) * ov;
                        store_h_splits(h2f, r, j, hv);
                        if (s == SEQ - 1) hf32[r * NB + j] = hv;
                    }
            }
        if (s + 1 < SEQ && tid < NB) xs[tid] = x[(base + tid) * SEQ + (s + 1)];
        __syncthreads();   // h2f(s+1) visible before next step's B loads
    }

    // final projection: out[b][c] = wph[c][:] . h[:, j] + bp[c]
    if (tid < NB * C_OUT) {
        const int j = tid / C_OUT;
        const int cls = tid - j * C_OUT;
        float accp = bp[cls];
#pragma unroll 8
        for (int k = 0; k < HID; k++) accp += wph[cls * HID + k] * hf32[k * NB + j];
        out[(base + j) * C_OUT + cls] = accp;
    }
}

extern "C" void kernel_launch(void* const* d_in, const int* in_sizes, int n_in,
                              void* d_out, int out_size) {
    const float* x      = (const float*)d_in[0];
    const float* wgx    = (const float*)d_in[1];
    const float* wix    = (const float*)d_in[2];
    const float* wfx    = (const float*)d_in[3];
    const float* wox    = (const float*)d_in[4];
    const float* wgh    = (const float*)d_in[5];
    const float* wih    = (const float*)d_in[6];
    const float* wfh    = (const float*)d_in[7];
    const float* woh    = (const float*)d_in[8];
    const float* bg     = (const float*)d_in[9];
    const float* bi     = (const float*)d_in[10];
    const float* bf     = (const float*)d_in[11];
    const float* bo     = (const float*)d_in[12];
    const float* wph    = (const float*)d_in[13];
    const float* bp     = (const float*)d_in[14];
    const float* h_init = (const float*)d_in[15];
    const float* c_init = (const float*)d_in[16];
    float* out = (float*)d_out;

    cudaFuncSetAttribute(lstm_mma_kernel, cudaFuncAttributeMaxDynamicSharedMemorySize, SM_TOTAL);

    prepack_kernel<<<(CHUNKS_PER_STEP * 16384) / 256, 256>>>(wgh, wih, wfh, woh);
    lstm_mma_kernel<<<NCTA, NTHR, SM_TOTAL>>>(x, wgx, wix, wfx, wox, bg, bi, bf, bo,
                                              wph, bp, h_init, c_init, out);
}